// round 6
// baseline (speedup 1.0000x reference)
#include <cuda_runtime.h>
#include <cuda_bf16.h>
#include <math.h>

#define MAXN   8192
#define FDIM   128
#define HDIM   64
#define NB     48
#define TA     8          // atoms per block (phase 1)
#define NBLK   768        // 6144/8 == 48*16  (same grid for both phases)
#define SPLIT  16         // blocks per molecule (phase 2)
#define MAXSEG 320
#define QSCALE 3.7946016f // sqrt(14.399)

// ---------------- device scratch (zero-init; winner restores each run) ------
__device__ int    g_arrive;
__device__ float  g_qsum[NB];        // sum of q*QSCALE per molecule
__device__ float  g_emol[NB];
__device__ int    g_mdone[NB];
__device__ int    g_done;
__device__ int    g_start[NB];
__device__ int    g_end[NB];
__device__ __align__(16) float g_p1[MAXN * 4];   // {x, y, z, q*QSCALE}
__device__ __align__(16) float g_p2[MAXN * 4];   // {mux, muy, muz, sqrt_c6}

// ---------------- f32x2 helpers ---------------------------------------------
__device__ __forceinline__ unsigned long long pack2(float lo, float hi) {
    unsigned long long r;
    asm("mov.b64 %0, {%1, %2};" : "=l"(r) : "f"(lo), "f"(hi));
    return r;
}
__device__ __forceinline__ void unpack2(unsigned long long v, float& lo, float& hi) {
    asm("mov.b64 {%0, %1}, %2;" : "=f"(lo), "=f"(hi) : "l"(v));
}
__device__ __forceinline__ void ffma2(unsigned long long& d, unsigned long long a,
                                      unsigned long long b, unsigned long long c) {
    asm("fma.rn.f32x2 %0, %1, %2, %3;" : "=l"(d) : "l"(a), "l"(b), "l"(c));
}
__device__ __forceinline__ void lds_v2_u64(unsigned long long& a, unsigned long long& b,
                                           unsigned int smem_addr) {
    asm("ld.shared.v2.u64 {%0, %1}, [%2];" : "=l"(a), "=l"(b) : "r"(smem_addr));
}

// smem layout (union by offset):
//  phase1: [0,4096) h0 tile, [4096,16384) h1 tile, [16384,16512) part
//  phase2: [0,5120) sA float4[320], [5120,10240) sB float4[320], [10240,...) wred
#define SMEM_BYTES 16544

__global__ __launch_bounds__(128) void fused_kernel(
    const float* __restrict__ h0, const float* __restrict__ h1,
    const float* __restrict__ pos, const int* __restrict__ batch,
    const float* __restrict__ qW1, const float* __restrict__ qb1,
    const float* __restrict__ qW2, const float* __restrict__ qb2,
    const float* __restrict__ cW1, const float* __restrict__ cb1,
    const float* __restrict__ cW2, const float* __restrict__ cb2,
    const float* __restrict__ muW, float* __restrict__ out, int N)
{
    __shared__ __align__(16) char sm[SMEM_BYTES];
    int t    = threadIdx.x;
    int bid  = blockIdx.x;
    int warp = t >> 5, lane = t & 31;

    // ======================= PHASE 1: features ==============================
    {
        int a0 = bid * TA;

        float4* h0d = (float4*)sm;                         // 8x128 floats
        float*  h1f = (float*)(sm + 4096);                 // 24x128 floats
        float*  part = (float*)(sm + 16384);               // [4][8]

        // prefetch (independent LDGs batched up-front)
        float px = 0.f, py = 0.f, pz = 0.f;
        if (t < TA) {
            px = pos[(a0 + t) * 3 + 0];
            py = pos[(a0 + t) * 3 + 1];
            pz = pos[(a0 + t) * 3 + 2];
        }
        float mw0 = muW[lane], mw1 = muW[lane + 32];
        float mw2 = muW[lane + 64], mw3 = muW[lane + 96];

        // stage h0 tile: 256 float4
        {
            const float4* src = (const float4*)(h0 + (size_t)a0 * FDIM);
            h0d[t]       = src[t];
            h0d[t + 128] = src[t + 128];
        }
        // stage h1 tile: 768 float4
        {
            const float4* src = (const float4*)(h1 + (size_t)a0 * 3 * FDIM);
            float4* dst = (float4*)h1f;
            #pragma unroll
            for (int k = 0; k < 6; k++) dst[t + k * 128] = src[t + k * 128];
        }
        // segment boundaries (batch sorted)
        if (t < TA) {
            int i  = a0 + t;
            int bi = batch[i];
            if (i == 0 || batch[i - 1] != bi) g_start[bi] = i;
            if (i == N - 1 || batch[i + 1] != bi) g_end[bi] = i + 1;
        }
        __syncthreads();

        // ---- dual 64-wide MLP via packed f32x2 ----
        int mlp = t >> 6;         // 0 = q, 1 = c
        int hu  = t & 63;
        const float* W1 = mlp ? cW1 : qW1;
        const float* B1 = mlp ? cb1 : qb1;
        const float* W2 = mlp ? cW2 : qW2;

        unsigned int h0s_base = (unsigned int)__cvta_generic_to_shared(sm);
        unsigned long long acc[TA];
        #pragma unroll
        for (int a = 0; a < TA; a++) acc[a] = 0ull;

        #pragma unroll 4
        for (int f0 = 0; f0 < FDIM; f0 += 4) {
            const float* wp = W1 + f0 * HDIM + hu;
            float wa = wp[0];
            float wb = wp[HDIM];
            float wc = wp[2 * HDIM];
            float wd = wp[3 * HDIM];
            unsigned long long w01 = pack2(wa, wb);
            unsigned long long w23 = pack2(wc, wd);
            unsigned int addr = h0s_base + f0 * 4;
            #pragma unroll
            for (int a = 0; a < TA; a++) {
                unsigned long long hA, hB;
                lds_v2_u64(hA, hB, addr + a * (FDIM * 4));   // uniform -> broadcast
                ffma2(acc[a], hA, w01, acc[a]);
                ffma2(acc[a], hB, w23, acc[a]);
            }
        }

        float b1v = B1[hu];
        float w2v = W2[hu];
        #pragma unroll
        for (int a = 0; a < TA; a++) {
            float p0, p1;
            unpack2(acc[a], p0, p1);
            float pre = p0 + p1 + b1v;
            float v   = (pre / (1.0f + __expf(-pre))) * w2v;   // silu * W2
            #pragma unroll
            for (int off = 16; off >= 1; off >>= 1)
                v += __shfl_xor_sync(0xffffffffu, v, off);
            if (lane == 0) part[warp * TA + a] = v;
        }
        __syncthreads();

        if (t < 2 * TA) {
            int m2 = t >> 3, a = t & 7;
            float sum = part[2 * m2 * TA + a] + part[(2 * m2 + 1) * TA + a];
            if (m2 == 0) {
                float qs = (sum + qb2[0]) * QSCALE;
                ((float4*)g_p1)[a0 + a] = make_float4(px, py, pz, qs);
                atomicAdd(&g_qsum[batch[a0 + a]], qs);
            } else {
                float c_raw = sum + cb2[0];
                float sp = (c_raw > 20.0f) ? c_raw : log1pf(__expf(c_raw));
                g_p2[(a0 + a) * 4 + 3] = sqrtf(sp);
            }
        }

        // ---- mu: 24 rows from smem, batch all LDS before reducing ----
        float vv[6];
        #pragma unroll
        for (int kk = 0; kk < 6; kk++) {
            int r = warp + 4 * kk;
            const float* row = h1f + r * FDIM;
            vv[kk] = row[lane] * mw0 + row[lane + 32] * mw1
                   + row[lane + 64] * mw2 + row[lane + 96] * mw3;
        }
        #pragma unroll
        for (int off = 16; off >= 1; off >>= 1) {
            #pragma unroll
            for (int kk = 0; kk < 6; kk++)
                vv[kk] += __shfl_xor_sync(0xffffffffu, vv[kk], off);
        }
        if (lane == 0) {
            #pragma unroll
            for (int kk = 0; kk < 6; kk++) {
                int r = warp + 4 * kk;
                g_p2[(a0 + r / 3) * 4 + (r % 3)] = vv[kk];
            }
        }
    }

    // ======================= grid barrier ===================================
    __threadfence();
    __syncthreads();
    if (t == 0) {
        atomicAdd(&g_arrive, 1);
        while (*(volatile int*)&g_arrive < NBLK) __nanosleep(32);
    }
    __syncthreads();
    __threadfence();

    // ======================= PHASE 2: pair energy ===========================
    {
        int b     = bid >> 4;        // molecule
        int slice = bid & 15;

        float4* sA = (float4*)sm;
        float4* sB = (float4*)(sm + 5120);
        float*  wred = (float*)(sm + 10240);

        int s = g_start[b];
        int e = g_end[b];
        int m = e - s;
        if (m > MAXSEG) m = MAXSEG;

        float accE = 0.0f;
        if (m > 0) {
            float qmeanS = g_qsum[b] / (float)m;
            for (int k = t; k < m; k += 128) {
                float4 A = ((const float4*)g_p1)[s + k];
                A.w -= qmeanS;
                sA[k] = A;
                sB[k] = ((const float4*)g_p2)[s + k];
            }
            __syncthreads();

            const int W = SPLIT * 4;            // 64 warps per molecule
            int wm = slice * 4 + warp;

            for (int k = 0; k * W < m; k++) {
                int i = (k & 1) ? ((k + 1) * W - 1 - wm) : (k * W + wm);
                if (i >= m - 1) continue;
                float4 Ai = sA[i];
                float4 Bi = sB[i];

                for (int j = i + 1 + lane; j < m; j += 32) {
                    float4 Aj = sA[j];
                    float4 Bj = sB[j];
                    float dx = Ai.x - Aj.x;
                    float dy = Ai.y - Aj.y;
                    float dz = Ai.z - Aj.z;
                    float d2 = fmaf(dx, dx, fmaf(dy, dy, dz * dz));
                    float d2e = d2 + 1e-8f;
                    float invd = rsqrtf(d2e);
                    float dist = d2e * invd;

                    // Coulomb (sqrt(14.399) folded into both q's)
                    float taper = 1.0f - __expf(-0.5f * dist);
                    float ev = Ai.w * Aj.w * invd * taper;

                    // vdW
                    float r6 = d2 * d2 * d2;
                    ev -= __fdividef(Bi.w * Bj.w, r6 + 20.0f);

                    // dipole-dipole
                    float mm  = Bi.x * Bj.x + Bi.y * Bj.y + Bi.z * Bj.z;
                    float mdi = Bi.x * dx + Bi.y * dy + Bi.z * dz;
                    float mdj = Bj.x * dx + Bj.y * dy + Bj.z * dz;
                    float num = mm - 3.0f * mdi * mdj * invd * invd;
                    ev += __fdividef(num, d2 * dist + 10.0f);

                    accE += ev;
                }
            }
        }

        // block reduce
        #pragma unroll
        for (int off = 16; off >= 1; off >>= 1)
            accE += __shfl_xor_sync(0xffffffffu, accE, off);
        if (lane == 0) wred[warp] = accE;
        __syncthreads();

        if (t == 0) {
            float tot = wred[0] + wred[1] + wred[2] + wred[3];
            atomicAdd(&g_emol[b], tot);
            __threadfence();
            if (atomicAdd(&g_mdone[b], 1) == SPLIT - 1) {
                __threadfence();
                if (atomicAdd(&g_done, 1) == NB - 1) {
                    __threadfence();
                    double E = 0.0;
                    #pragma unroll
                    for (int i = 0; i < NB; i++) E += (double)g_emol[i];
                    out[0] = (float)E;
                    // restore pristine state for the next graph replay
                    #pragma unroll
                    for (int i = 0; i < NB; i++) {
                        g_emol[i]  = 0.0f;
                        g_mdone[i] = 0;
                        g_qsum[i]  = 0.0f;
                    }
                    g_done   = 0;
                    g_arrive = 0;
                }
            }
        }
    }
}

// ---------------- launch ----------------
extern "C" void kernel_launch(void* const* d_in, const int* in_sizes, int n_in,
                              void* d_out, int out_size)
{
    const float* h0    = (const float*)d_in[0];
    const float* h1    = (const float*)d_in[1];
    const float* pos   = (const float*)d_in[2];
    const int*   batch = (const int*)  d_in[3];
    const float* qW1   = (const float*)d_in[4];
    const float* qb1   = (const float*)d_in[5];
    const float* qW2   = (const float*)d_in[6];
    const float* qb2   = (const float*)d_in[7];
    const float* cW1   = (const float*)d_in[8];
    const float* cb1   = (const float*)d_in[9];
    const float* cW2   = (const float*)d_in[10];
    const float* cb2   = (const float*)d_in[11];
    const float* muW   = (const float*)d_in[12];

    int N = in_sizes[3];

    fused_kernel<<<NBLK, 128>>>(h0, h1, pos, batch, qW1, qb1, qW2, qb2,
                                cW1, cb1, cW2, cb2, muW, (float*)d_out, N);
}

// round 7
// speedup vs baseline: 1.1482x; 1.1482x over previous
#include <cuda_runtime.h>
#include <cuda_bf16.h>
#include <math.h>

#define MAXN   8192
#define FDIM   128
#define HDIM   64
#define NB     48
#define TA     8         // atoms per feature block
#define MAXSEG 320       // max atoms per molecule (mean 128, sd ~11)
#define SPLIT  16        // blocks per molecule in pair kernel
#define QSCALE 3.7946016f   // sqrt(14.399)

// ---------------- device scratch (zero-init; reset by features blk 0) -------
__device__ double g_energy;
__device__ int    g_done;
__device__ int    g_start[NB];
__device__ int    g_end[NB];
__device__ __align__(16) float g_p1[MAXN * 4];   // {x, y, z, q*QSCALE}
__device__ __align__(16) float g_p2[MAXN * 4];   // {mux, muy, muz, sqrt_c6}

// ---------------- f32x2 helpers ---------------------------------------------
__device__ __forceinline__ unsigned long long pack2(float lo, float hi) {
    unsigned long long r;
    asm("mov.b64 %0, {%1, %2};" : "=l"(r) : "f"(lo), "f"(hi));
    return r;
}
__device__ __forceinline__ void unpack2(unsigned long long v, float& lo, float& hi) {
    asm("mov.b64 {%0, %1}, %2;" : "=f"(lo), "=f"(hi) : "l"(v));
}
__device__ __forceinline__ void ffma2(unsigned long long& d, unsigned long long a,
                                      unsigned long long b, unsigned long long c) {
    asm("fma.rn.f32x2 %0, %1, %2, %3;" : "=l"(d) : "l"(a), "l"(b), "l"(c));
}
__device__ __forceinline__ void lds_v2_u64(unsigned long long& a, unsigned long long& b,
                                           unsigned int smem_addr) {
    asm("ld.shared.v2.u64 {%0, %1}, [%2];" : "=l"(a), "=l"(b) : "r"(smem_addr));
}

// ================= features =================================================
// 128 threads, 8 atoms per block. Thread t: hidden unit t&63 of MLP t>>6.
__global__ __launch_bounds__(128) void features_kernel(
    const float* __restrict__ h0, const float* __restrict__ h1,
    const float* __restrict__ pos, const int* __restrict__ batch,
    const float* __restrict__ qW1, const float* __restrict__ qb1,
    const float* __restrict__ qW2, const float* __restrict__ qb2,
    const float* __restrict__ cW1, const float* __restrict__ cb1,
    const float* __restrict__ cW2, const float* __restrict__ cb2,
    const float* __restrict__ muW, int N)
{
    int t  = threadIdx.x;          // 0..127
    int a0 = blockIdx.x * TA;

    if (blockIdx.x == 0 && t == 0) { g_energy = 0.0; g_done = 0; }

    __shared__ __align__(16) float h0s[TA][FDIM];    // 4 KB
    __shared__ float part[4][TA];

    // prefetch this thread's pos row (t<8 -> atom a0+t; same thread writes g_p1)
    float px = 0.f, py = 0.f, pz = 0.f;
    if (t < TA) {
        px = pos[(a0 + t) * 3 + 0];
        py = pos[(a0 + t) * 3 + 1];
        pz = pos[(a0 + t) * 3 + 2];
    }

    // stage h0 tile: 256 float4, 128 threads -> 2 each (coalesced)
    {
        const float4* src = (const float4*)(h0 + (size_t)a0 * FDIM);
        float4* dst = (float4*)&h0s[0][0];
        dst[t]       = src[t];
        dst[t + 128] = src[t + 128];
    }

    // segment boundary detection (batch is sorted)
    if (t < TA) {
        int i  = a0 + t;
        int bi = batch[i];
        if (i == 0 || batch[i - 1] != bi) g_start[bi] = i;
        if (i == N - 1 || batch[i + 1] != bi) g_end[bi] = i + 1;
    }
    __syncthreads();

    int mlp = t >> 6;          // 0 = q, 1 = c
    int hu  = t & 63;
    int warp = t >> 5, lane = t & 31;
    const float* W1 = mlp ? cW1 : qW1;
    const float* B1 = mlp ? cb1 : qb1;
    const float* W2 = mlp ? cW2 : qW2;

    unsigned int h0s_base = (unsigned int)__cvta_generic_to_shared(&h0s[0][0]);

    // acc[a] holds {sum over even-pair f, sum over odd-pair f} packed f32x2
    unsigned long long acc[TA];
    #pragma unroll
    for (int a = 0; a < TA; a++) acc[a] = 0ull;

    #pragma unroll 4
    for (int f0 = 0; f0 < FDIM; f0 += 4) {
        const float* wp = W1 + f0 * HDIM + hu;
        float wa = wp[0];
        float wb = wp[HDIM];
        float wc = wp[2 * HDIM];
        float wd = wp[3 * HDIM];
        unsigned long long w01 = pack2(wa, wb);
        unsigned long long w23 = pack2(wc, wd);
        unsigned int addr = h0s_base + f0 * 4;
        #pragma unroll
        for (int a = 0; a < TA; a++) {
            unsigned long long hA, hB;
            lds_v2_u64(hA, hB, addr + a * (FDIM * 4));   // uniform -> broadcast
            ffma2(acc[a], hA, w01, acc[a]);
            ffma2(acc[a], hB, w23, acc[a]);
        }
    }

    float b1v = B1[hu];
    float w2v = W2[hu];
    #pragma unroll
    for (int a = 0; a < TA; a++) {
        float p0, p1;
        unpack2(acc[a], p0, p1);
        float pre = p0 + p1 + b1v;
        float v   = (pre / (1.0f + __expf(-pre))) * w2v;   // silu * W2
        #pragma unroll
        for (int off = 16; off >= 1; off >>= 1)
            v += __shfl_xor_sync(0xffffffffu, v, off);
        if (lane == 0) part[warp][a] = v;
    }
    __syncthreads();

    if (t < 2 * TA) {
        int m2 = t >> 3, a = t & 7;    // m2: 0=q, 1=c
        float sum = part[2 * m2][a] + part[2 * m2 + 1][a];
        if (m2 == 0) {
            // t == a here (t < 8), so px/py/pz belong to this atom
            float qs = (sum + qb2[0]) * QSCALE;
            ((float4*)g_p1)[a0 + a] = make_float4(px, py, pz, qs);
        } else {
            float c_raw = sum + cb2[0];
            float sp = (c_raw > 20.0f) ? c_raw : log1pf(__expf(c_raw));
            g_p2[(a0 + a) * 4 + 3] = sqrtf(sp);
        }
    }

    // mu[d] = h1[atom,d,:] . muW  -- 24 rows, 4 warps -> 6 rows each
    float mw0 = muW[lane], mw1 = muW[lane + 32];
    float mw2 = muW[lane + 64], mw3 = muW[lane + 96];
    float vv[6];
    #pragma unroll
    for (int kk = 0; kk < 6; kk++) {
        int r = warp + 4 * kk;
        const float* row = h1 + ((size_t)a0 * 3 + r) * FDIM;
        vv[kk] = row[lane] * mw0 + row[lane + 32] * mw1
               + row[lane + 64] * mw2 + row[lane + 96] * mw3;
    }
    #pragma unroll
    for (int off = 16; off >= 1; off >>= 1) {
        #pragma unroll
        for (int kk = 0; kk < 6; kk++)
            vv[kk] += __shfl_xor_sync(0xffffffffu, vv[kk], off);
    }
    if (lane == 0) {
        #pragma unroll
        for (int kk = 0; kk < 6; kk++) {
            int r = warp + 4 * kk;
            g_p2[(a0 + r / 3) * 4 + (r % 3)] = vv[kk];
        }
    }
}

// ================= pairwise energy (R3 structure, packed staging) ===========
// 128 threads. SPLIT blocks per molecule; warp owns rows i (boustrophedon),
// lanes stride over j > i.
__global__ __launch_bounds__(128) void pair_kernel(float* __restrict__ out)
{
    int b     = blockIdx.x / SPLIT;
    int slice = blockIdx.x % SPLIT;
    int t     = threadIdx.x;
    int warp  = t >> 5, lane = t & 31;

    __shared__ float4 sA[MAXSEG];   // {x, y, z, (q - qmean)*QSCALE}
    __shared__ float4 sB[MAXSEG];   // {mux, muy, muz, sqrt_c6}
    __shared__ float  wred[4];
    __shared__ float  s_qmeanS;

    int s = g_start[b];
    int e = g_end[b];
    int m = e - s;
    if (m > MAXSEG) m = MAXSEG;

    float accE = 0.0f;
    if (m > 0) {
        for (int k = t; k < m; k += 128) {
            sA[k] = ((const float4*)g_p1)[s + k];
            sB[k] = ((const float4*)g_p2)[s + k];
        }
        __syncthreads();

        // scaled q mean over segment
        float ls = 0.0f;
        for (int k = t; k < m; k += 128) ls += sA[k].w;
        #pragma unroll
        for (int off = 16; off >= 1; off >>= 1)
            ls += __shfl_xor_sync(0xffffffffu, ls, off);
        if (lane == 0) wred[warp] = ls;
        __syncthreads();
        if (t == 0)
            s_qmeanS = (wred[0] + wred[1] + wred[2] + wred[3]) / (float)m;
        __syncthreads();
        float qmeanS = s_qmeanS;
        for (int k = t; k < m; k += 128) sA[k].w -= qmeanS;
        __syncthreads();

        const int W = SPLIT * 4;             // 64 warps per molecule
        int wm = slice * 4 + warp;

        for (int k = 0; k * W < m; k++) {
            int i = (k & 1) ? ((k + 1) * W - 1 - wm) : (k * W + wm);
            if (i >= m - 1) continue;
            float4 Ai = sA[i];
            float4 Bi = sB[i];

            for (int j = i + 1 + lane; j < m; j += 32) {
                float4 Aj = sA[j];
                float4 Bj = sB[j];
                float dx = Ai.x - Aj.x;
                float dy = Ai.y - Aj.y;
                float dz = Ai.z - Aj.z;
                float d2 = fmaf(dx, dx, fmaf(dy, dy, dz * dz));
                float d2e = d2 + 1e-8f;
                float invd = rsqrtf(d2e);
                float dist = d2e * invd;

                // Coulomb (sqrt(14.399) folded into both q's)
                float taper = 1.0f - __expf(-0.5f * dist);
                float ev = Ai.w * Aj.w * invd * taper;

                // vdW
                float r6 = d2 * d2 * d2;
                ev -= __fdividef(Bi.w * Bj.w, r6 + 20.0f);

                // dipole-dipole
                float mm  = Bi.x * Bj.x + Bi.y * Bj.y + Bi.z * Bj.z;
                float mdi = Bi.x * dx + Bi.y * dy + Bi.z * dz;
                float mdj = Bj.x * dx + Bj.y * dy + Bj.z * dz;
                float num = mm - 3.0f * mdi * mdj * invd * invd;
                ev += __fdividef(num, d2 * dist + 10.0f);

                accE += ev;
            }
        }
    }

    // block reduce
    #pragma unroll
    for (int off = 16; off >= 1; off >>= 1)
        accE += __shfl_xor_sync(0xffffffffu, accE, off);
    __syncthreads();
    if (lane == 0) wred[warp] = accE;
    __syncthreads();

    if (t == 0) {
        atomicAdd(&g_energy, (double)(wred[0] + wred[1] + wred[2] + wred[3]));
        __threadfence();
        int done = atomicAdd(&g_done, 1);
        if (done == (int)gridDim.x - 1)
            out[0] = (float)g_energy;
    }
}

// ---------------- launch ----------------
extern "C" void kernel_launch(void* const* d_in, const int* in_sizes, int n_in,
                              void* d_out, int out_size)
{
    const float* h0    = (const float*)d_in[0];
    const float* h1    = (const float*)d_in[1];
    const float* pos   = (const float*)d_in[2];
    const int*   batch = (const int*)  d_in[3];
    const float* qW1   = (const float*)d_in[4];
    const float* qb1   = (const float*)d_in[5];
    const float* qW2   = (const float*)d_in[6];
    const float* qb2   = (const float*)d_in[7];
    const float* cW1   = (const float*)d_in[8];
    const float* cb1   = (const float*)d_in[9];
    const float* cW2   = (const float*)d_in[10];
    const float* cb2   = (const float*)d_in[11];
    const float* muW   = (const float*)d_in[12];

    int N = in_sizes[3];

    features_kernel<<<N / TA, 128>>>(h0, h1, pos, batch, qW1, qb1, qW2, qb2,
                                     cW1, cb1, cW2, cb2, muW, N);
    pair_kernel<<<NB * SPLIT, 128>>>((float*)d_out);
}

// round 9
// speedup vs baseline: 1.3574x; 1.1822x over previous
#include <cuda_runtime.h>
#include <cuda_bf16.h>
#include <math.h>

#define MAXN   8192
#define FDIM   128
#define HDIM   64
#define NB     48
#define TA     16        // atoms per feature block (two 8-atom halves)
#define MAXSEG 320       // max atoms per molecule (mean 128, sd ~11)
#define SPLIT  32        // blocks per molecule in pair kernel
#define QSCALE 3.7946016f   // sqrt(14.399)

// ---------------- device scratch (zero-init; reset by features blk 0) -------
__device__ double g_energy;
__device__ int    g_done;
__device__ int    g_start[NB];
__device__ int    g_end[NB];
__device__ __align__(16) float g_p1[MAXN * 4];   // {x, y, z, q*QSCALE}
__device__ __align__(16) float g_p2[MAXN * 4];   // {mux, muy, muz, sqrt_c6}

// ---------------- f32x2 helpers ---------------------------------------------
__device__ __forceinline__ unsigned long long pack2(float lo, float hi) {
    unsigned long long r;
    asm("mov.b64 %0, {%1, %2};" : "=l"(r) : "f"(lo), "f"(hi));
    return r;
}
__device__ __forceinline__ void unpack2(unsigned long long v, float& lo, float& hi) {
    asm("mov.b64 {%0, %1}, %2;" : "=f"(lo), "=f"(hi) : "l"(v));
}
__device__ __forceinline__ void ffma2(unsigned long long& d, unsigned long long a,
                                      unsigned long long b, unsigned long long c) {
    asm("fma.rn.f32x2 %0, %1, %2, %3;" : "=l"(d) : "l"(a), "l"(b), "l"(c));
}
__device__ __forceinline__ void lds_v2_u64(unsigned long long& a, unsigned long long& b,
                                           unsigned int smem_addr) {
    asm("ld.shared.v2.u64 {%0, %1}, [%2];" : "=l"(a), "=l"(b) : "r"(smem_addr));
}

// ================= features =================================================
// 256 threads = two independent 128-thread halves; each half: 8 atoms,
// thread ht: hidden unit ht&63 of MLP ht>>6.
__global__ __launch_bounds__(256) void features_kernel(
    const float* __restrict__ h0, const float* __restrict__ h1,
    const float* __restrict__ pos, const int* __restrict__ batch,
    const float* __restrict__ qW1, const float* __restrict__ qb1,
    const float* __restrict__ qW2, const float* __restrict__ qb2,
    const float* __restrict__ cW1, const float* __restrict__ cb1,
    const float* __restrict__ cW2, const float* __restrict__ cb2,
    const float* __restrict__ muW, int N)
{
    int t    = threadIdx.x;          // 0..255
    int half = t >> 7;               // 0 or 1
    int ht   = t & 127;
    int a0   = blockIdx.x * TA;      // block's first atom
    int a0h  = a0 + half * 8;        // this half's first atom

    if (blockIdx.x == 0 && t == 0) { g_energy = 0.0; g_done = 0; }

    __shared__ __align__(16) float h0s[TA][FDIM];    // 8 KB
    __shared__ float part[8][8];                     // [warp][atom-in-half]

    // prefetch pos for this half's atom ht (same thread writes g_p1 later)
    float px = 0.f, py = 0.f, pz = 0.f;
    if (ht < 8) {
        px = pos[(a0h + ht) * 3 + 0];
        py = pos[(a0h + ht) * 3 + 1];
        pz = pos[(a0h + ht) * 3 + 2];
    }

    // stage h0 tile: 512 float4, 256 threads -> 2 each (coalesced)
    {
        const float4* src = (const float4*)(h0 + (size_t)a0 * FDIM);
        float4* dst = (float4*)&h0s[0][0];
        dst[t]       = src[t];
        dst[t + 256] = src[t + 256];
    }

    // segment boundary detection (batch is sorted)
    if (t < TA) {
        int i  = a0 + t;
        int bi = batch[i];
        if (i == 0 || batch[i - 1] != bi) g_start[bi] = i;
        if (i == N - 1 || batch[i + 1] != bi) g_end[bi] = i + 1;
    }
    __syncthreads();

    int mlp = ht >> 6;          // 0 = q, 1 = c
    int hu  = ht & 63;
    int warp = t >> 5, lane = t & 31;
    const float* W1 = mlp ? cW1 : qW1;
    const float* B1 = mlp ? cb1 : qb1;
    const float* W2 = mlp ? cW2 : qW2;

    unsigned int hbase = (unsigned int)__cvta_generic_to_shared(&h0s[0][0])
                       + half * 8 * (FDIM * 4);

    unsigned long long acc[8];
    #pragma unroll
    for (int a = 0; a < 8; a++) acc[a] = 0ull;

    #pragma unroll 4
    for (int f0 = 0; f0 < FDIM; f0 += 4) {
        const float* wp = W1 + f0 * HDIM + hu;
        float wa = wp[0];
        float wb = wp[HDIM];
        float wc = wp[2 * HDIM];
        float wd = wp[3 * HDIM];
        unsigned long long w01 = pack2(wa, wb);
        unsigned long long w23 = pack2(wc, wd);
        unsigned int addr = hbase + f0 * 4;
        #pragma unroll
        for (int a = 0; a < 8; a++) {
            unsigned long long hA, hB;
            lds_v2_u64(hA, hB, addr + a * (FDIM * 4));   // uniform -> broadcast
            ffma2(acc[a], hA, w01, acc[a]);
            ffma2(acc[a], hB, w23, acc[a]);
        }
    }

    // epilogue: silu * W2, then 8 INTERLEAVED shuffle-reduce chains
    float b1v = B1[hu];
    float w2v = W2[hu];
    float v[8];
    #pragma unroll
    for (int a = 0; a < 8; a++) {
        float p0, p1;
        unpack2(acc[a], p0, p1);
        float pre = p0 + p1 + b1v;
        v[a] = (pre / (1.0f + __expf(-pre))) * w2v;
    }
    #pragma unroll
    for (int off = 16; off >= 1; off >>= 1) {
        #pragma unroll
        for (int a = 0; a < 8; a++)
            v[a] += __shfl_xor_sync(0xffffffffu, v[a], off);
    }
    if (lane == 0) {
        #pragma unroll
        for (int a = 0; a < 8; a++) part[warp][a] = v[a];
    }
    __syncthreads();

    if (ht < 16) {
        int m2 = ht >> 3, a = ht & 7;    // m2: 0=q, 1=c
        float sum = part[half * 4 + 2 * m2][a] + part[half * 4 + 2 * m2 + 1][a];
        if (m2 == 0) {
            // ht == a here, so px/py/pz belong to atom a0h + a
            float qs = (sum + qb2[0]) * QSCALE;
            ((float4*)g_p1)[a0h + a] = make_float4(px, py, pz, qs);
        } else {
            float c_raw = sum + cb2[0];
            float sp = (c_raw > 20.0f) ? c_raw : log1pf(__expf(c_raw));
            g_p2[(a0h + a) * 4 + 3] = sqrtf(sp);
        }
    }

    // mu[d] = h1[atom,d,:] . muW  -- 48 rows, 8 warps -> 6 rows each, batched
    float mw0 = muW[lane], mw1 = muW[lane + 32];
    float mw2 = muW[lane + 64], mw3 = muW[lane + 96];
    float vv[6];
    #pragma unroll
    for (int kk = 0; kk < 6; kk++) {
        int r = warp + 8 * kk;
        const float* row = h1 + ((size_t)a0 * 3 + r) * FDIM;
        vv[kk] = row[lane] * mw0 + row[lane + 32] * mw1
               + row[lane + 64] * mw2 + row[lane + 96] * mw3;
    }
    #pragma unroll
    for (int off = 16; off >= 1; off >>= 1) {
        #pragma unroll
        for (int kk = 0; kk < 6; kk++)
            vv[kk] += __shfl_xor_sync(0xffffffffu, vv[kk], off);
    }
    if (lane == 0) {
        #pragma unroll
        for (int kk = 0; kk < 6; kk++) {
            int r = warp + 8 * kk;
            g_p2[(a0 + r / 3) * 4 + (r % 3)] = vv[kk];
        }
    }
}

// ================= pairwise energy ==========================================
// 128 threads. SPLIT blocks per molecule; warp owns rows i (boustrophedon),
// lanes stride over j > i.
__global__ __launch_bounds__(128) void pair_kernel(float* __restrict__ out)
{
    int b     = blockIdx.x / SPLIT;
    int slice = blockIdx.x % SPLIT;
    int t     = threadIdx.x;
    int warp  = t >> 5, lane = t & 31;

    __shared__ float4 sA[MAXSEG];   // {x, y, z, (q - qmean)*QSCALE}
    __shared__ float4 sB[MAXSEG];   // {mux, muy, muz, sqrt_c6}
    __shared__ float  wred[4];
    __shared__ float  s_qmeanS;

    int s = g_start[b];
    int e = g_end[b];
    int m = e - s;
    if (m > MAXSEG) m = MAXSEG;

    float accE = 0.0f;
    if (m > 0) {
        for (int k = t; k < m; k += 128) {
            sA[k] = ((const float4*)g_p1)[s + k];
            sB[k] = ((const float4*)g_p2)[s + k];
        }
        __syncthreads();

        // scaled q mean over segment
        float ls = 0.0f;
        for (int k = t; k < m; k += 128) ls += sA[k].w;
        #pragma unroll
        for (int off = 16; off >= 1; off >>= 1)
            ls += __shfl_xor_sync(0xffffffffu, ls, off);
        if (lane == 0) wred[warp] = ls;
        __syncthreads();
        if (t == 0)
            s_qmeanS = (wred[0] + wred[1] + wred[2] + wred[3]) / (float)m;
        __syncthreads();
        float qmeanS = s_qmeanS;
        for (int k = t; k < m; k += 128) sA[k].w -= qmeanS;
        __syncthreads();

        const int W = SPLIT * 4;             // 128 warps per molecule
        int wm = slice * 4 + warp;

        for (int k = 0; k * W < m; k++) {
            int i = (k & 1) ? ((k + 1) * W - 1 - wm) : (k * W + wm);
            if (i >= m - 1) continue;
            float4 Ai = sA[i];
            float4 Bi = sB[i];

            #pragma unroll 2
            for (int j = i + 1 + lane; j < m; j += 32) {
                float4 Aj = sA[j];
                float4 Bj = sB[j];
                float dx = Ai.x - Aj.x;
                float dy = Ai.y - Aj.y;
                float dz = Ai.z - Aj.z;
                float d2 = fmaf(dx, dx, fmaf(dy, dy, dz * dz));
                float d2e = d2 + 1e-8f;
                float invd = rsqrtf(d2e);
                float dist = d2e * invd;

                // Coulomb (sqrt(14.399) folded into both q's)
                float taper = 1.0f - __expf(-0.5f * dist);
                float ev = Ai.w * Aj.w * invd * taper;

                // vdW
                float r6 = d2 * d2 * d2;
                ev -= __fdividef(Bi.w * Bj.w, r6 + 20.0f);

                // dipole-dipole
                float mm  = Bi.x * Bj.x + Bi.y * Bj.y + Bi.z * Bj.z;
                float mdi = Bi.x * dx + Bi.y * dy + Bi.z * dz;
                float mdj = Bj.x * dx + Bj.y * dy + Bj.z * dz;
                float num = mm - 3.0f * mdi * mdj * invd * invd;
                ev += __fdividef(num, d2 * dist + 10.0f);

                accE += ev;
            }
        }
    }

    // block reduce
    #pragma unroll
    for (int off = 16; off >= 1; off >>= 1)
        accE += __shfl_xor_sync(0xffffffffu, accE, off);
    __syncthreads();
    if (lane == 0) wred[warp] = accE;
    __syncthreads();

    if (t == 0) {
        atomicAdd(&g_energy, (double)(wred[0] + wred[1] + wred[2] + wred[3]));
        __threadfence();
        int done = atomicAdd(&g_done, 1);
        if (done == (int)gridDim.x - 1)
            out[0] = (float)g_energy;
    }
}

// ---------------- launch ----------------
extern "C" void kernel_launch(void* const* d_in, const int* in_sizes, int n_in,
                              void* d_out, int out_size)
{
    const float* h0    = (const float*)d_in[0];
    const float* h1    = (const float*)d_in[1];
    const float* pos   = (const float*)d_in[2];
    const int*   batch = (const int*)  d_in[3];
    const float* qW1   = (const float*)d_in[4];
    const float* qb1   = (const float*)d_in[5];
    const float* qW2   = (const float*)d_in[6];
    const float* qb2   = (const float*)d_in[7];
    const float* cW1   = (const float*)d_in[8];
    const float* cb1   = (const float*)d_in[9];
    const float* cW2   = (const float*)d_in[10];
    const float* cb2   = (const float*)d_in[11];
    const float* muW   = (const float*)d_in[12];

    int N = in_sizes[3];

    features_kernel<<<N / TA, 256>>>(h0, h1, pos, batch, qW1, qb1, qW2, qb2,
                                     cW1, cb1, cW2, cb2, muW, N);
    pair_kernel<<<NB * SPLIT, 128>>>((float*)d_out);
}